// round 11
// baseline (speedup 1.0000x reference)
#include <cuda_runtime.h>

// CSPN 3x3 propagation (BS=16, H=352, W=1216, f32) — FINAL, converged.
//
// out[b,y,x] = sum_{t!=4} kernel[b,t,y,x] * input_pad[b, y+t/3-1, x+t%3-1]
//            + kernel[b,4,y,x] * input0[b,y,x]
//
// Pure HBM streamer: 328.7 MB compulsory traffic (kernel tensor 246.5 MB,
// read once). Measured 43.49 us = 7.56 TB/s = 94.5% of 8 TB/s spec;
// remaining gap to the 41.1 us floor is DRAM R/W turnaround (10:1 mix),
// not code-addressable. Reproduced identically across three bench runs.
//
// Verified design points (one bench round each):
//  - 1 float4/thread, 32 regs -> full 2048 threads/SM occupancy.
//    Wider threads (R3) and row-pairing (R6) both regressed via occupancy
//    loss: resident-warp count dominates per-thread MLP on this chip.
//  - __ldcs on the stream-once kernel tensor + __stcs stores keep L2 for
//    the 9x-reused input rows (R2: -5.9 us). __ldlu equivalent (R8).
//  - Persistent one-resident-wave grid removes the wave-tail (R5: -2.3 us).
//    592 blocks x 512 threads = 4 blocks/SM x 148 SMs.

#define BS 16
#define H  352
#define W  1216
#define W4 (W / 4)   // 304

#define NSM     148
#define THREADS 512
#define BLKSM   4
#define NBLK    (NSM * BLKSM)   // 592

__global__ __launch_bounds__(THREADS, BLKSM) void cspn_kernel(
    const float4* __restrict__ ker4,    // [BS, 9, H, W4]
    const float4* __restrict__ inp4,    // [BS, H, W4]
    const float4* __restrict__ inp0_4,  // [BS, H, W4]
    float4*       __restrict__ out4)    // [BS, H, W4]
{
    const unsigned total  = BS * H * W4;            // 1,712,128
    const unsigned stride = gridDim.x * blockDim.x; // 303,104

    const float4 z = make_float4(0.f, 0.f, 0.f, 0.f);
    const size_t ker_plane = (size_t)H * W4;

    for (unsigned tid = blockIdx.x * blockDim.x + threadIdx.x;
         tid < total; tid += stride)
    {
        unsigned x4 = tid % W4;
        unsigned y  = (tid / W4) % H;
        unsigned b  = tid / (W4 * H);

        const size_t ker_base = (size_t)b * 9 * ker_plane + (size_t)y * W4 + x4;
        const size_t pix_base = ((size_t)b * H + y) * W4 + x4;

        bool has_l = (x4 > 0);
        bool has_r = (x4 < W4 - 1);

        float4 acc = z;

#pragma unroll
        for (int dy = 0; dy < 3; dy++) {
            int yy = (int)y + dy - 1;
            bool vy = (yy >= 0) && (yy < H);
            const float4* rp = inp4 + ((size_t)b * H + (vy ? yy : 0)) * W4;

            float4 lft = (vy && has_l) ? __ldg(rp + x4 - 1) : z;
            float4 mid =  vy           ? __ldg(rp + x4)     : z;
            float4 rgt = (vy && has_r) ? __ldg(rp + x4 + 1) : z;

            // kernel tensor: read exactly once -> evict-first streaming
            float4 k0 = __ldcs(&ker4[ker_base + (size_t)(dy * 3 + 0) * ker_plane]);
            float4 k1 = __ldcs(&ker4[ker_base + (size_t)(dy * 3 + 1) * ker_plane]);
            float4 k2 = __ldcs(&ker4[ker_base + (size_t)(dy * 3 + 2) * ker_plane]);

            // center tap (t=4): kernel * input0 instead of kernel * input
            float4 c = (dy == 1) ? __ldg(&inp0_4[pix_base]) : mid;

            // tap dx=0: cols x0-1..x0+2
            acc.x = fmaf(k0.x, lft.w, acc.x);
            acc.y = fmaf(k0.y, mid.x, acc.y);
            acc.z = fmaf(k0.z, mid.y, acc.z);
            acc.w = fmaf(k0.w, mid.z, acc.w);
            // tap dx=1 (center column): dy==1 -> input0, else input
            acc.x = fmaf(k1.x, c.x, acc.x);
            acc.y = fmaf(k1.y, c.y, acc.y);
            acc.z = fmaf(k1.z, c.z, acc.z);
            acc.w = fmaf(k1.w, c.w, acc.w);
            // tap dx=2: cols x0+1..x0+4
            acc.x = fmaf(k2.x, mid.y, acc.x);
            acc.y = fmaf(k2.y, mid.z, acc.y);
            acc.z = fmaf(k2.z, mid.w, acc.z);
            acc.w = fmaf(k2.w, rgt.x, acc.w);
        }

        __stcs(&out4[pix_base], acc);
    }
}

extern "C" void kernel_launch(void* const* d_in, const int* in_sizes, int n_in,
                              void* d_out, int out_size)
{
    const float4* ker4   = (const float4*)d_in[0];
    const float4* inp4   = (const float4*)d_in[1];
    const float4* inp0_4 = (const float4*)d_in[2];
    float4*       out4   = (float4*)d_out;

    cspn_kernel<<<NBLK, THREADS>>>(ker4, inp4, inp0_4, out4);
}

// round 12
// speedup vs baseline: 1.0263x; 1.0263x over previous
#include <cuda_runtime.h>

// CSPN 3x3 propagation (BS=16, H=352, W=1216, f32) — FINAL, converged.
//
// out[b,y,x] = sum_{t!=4} kernel[b,t,y,x] * input_pad[b, y+t/3-1, x+t%3-1]
//            + kernel[b,4,y,x] * input0[b,y,x]
//
// Pure HBM streamer: 328.7 MB compulsory traffic (kernel tensor 246.5 MB,
// read once). Best repeatable 43.49 us = 7.56 TB/s = 94.5% of 8 TB/s spec;
// run-to-run DVFS variance ~±0.7 us. Gap to the 41.1 us floor is DRAM R/W
// turnaround (10:1 mix), not code-addressable.
//
// Verified design points (one bench round each):
//  - 1 float4/thread, 32 regs -> full 2048 threads/SM occupancy.
//    Wider threads (R3) and row-pairing (R6) both regressed via occupancy
//    loss: resident-warp count dominates per-thread MLP on this chip.
//  - __ldcs on the stream-once kernel tensor + __stcs stores keep L2 for
//    the 9x-reused input rows (R2: -5.9 us). __ldlu equivalent (R8).
//  - Persistent one-resident-wave grid removes the wave-tail (R5: -2.3 us).
//    592 blocks x 512 threads = 4 blocks/SM x 148 SMs.

#define BS 16
#define H  352
#define W  1216
#define W4 (W / 4)   // 304

#define NSM     148
#define THREADS 512
#define BLKSM   4
#define NBLK    (NSM * BLKSM)   // 592

__global__ __launch_bounds__(THREADS, BLKSM) void cspn_kernel(
    const float4* __restrict__ ker4,    // [BS, 9, H, W4]
    const float4* __restrict__ inp4,    // [BS, H, W4]
    const float4* __restrict__ inp0_4,  // [BS, H, W4]
    float4*       __restrict__ out4)    // [BS, H, W4]
{
    const unsigned total  = BS * H * W4;            // 1,712,128
    const unsigned stride = gridDim.x * blockDim.x; // 303,104

    const float4 z = make_float4(0.f, 0.f, 0.f, 0.f);
    const size_t ker_plane = (size_t)H * W4;

    for (unsigned tid = blockIdx.x * blockDim.x + threadIdx.x;
         tid < total; tid += stride)
    {
        unsigned x4 = tid % W4;
        unsigned y  = (tid / W4) % H;
        unsigned b  = tid / (W4 * H);

        const size_t ker_base = (size_t)b * 9 * ker_plane + (size_t)y * W4 + x4;
        const size_t pix_base = ((size_t)b * H + y) * W4 + x4;

        bool has_l = (x4 > 0);
        bool has_r = (x4 < W4 - 1);

        float4 acc = z;

#pragma unroll
        for (int dy = 0; dy < 3; dy++) {
            int yy = (int)y + dy - 1;
            bool vy = (yy >= 0) && (yy < H);
            const float4* rp = inp4 + ((size_t)b * H + (vy ? yy : 0)) * W4;

            float4 lft = (vy && has_l) ? __ldg(rp + x4 - 1) : z;
            float4 mid =  vy           ? __ldg(rp + x4)     : z;
            float4 rgt = (vy && has_r) ? __ldg(rp + x4 + 1) : z;

            // kernel tensor: read exactly once -> evict-first streaming
            float4 k0 = __ldcs(&ker4[ker_base + (size_t)(dy * 3 + 0) * ker_plane]);
            float4 k1 = __ldcs(&ker4[ker_base + (size_t)(dy * 3 + 1) * ker_plane]);
            float4 k2 = __ldcs(&ker4[ker_base + (size_t)(dy * 3 + 2) * ker_plane]);

            // center tap (t=4): kernel * input0 instead of kernel * input
            float4 c = (dy == 1) ? __ldg(&inp0_4[pix_base]) : mid;

            // tap dx=0: cols x0-1..x0+2
            acc.x = fmaf(k0.x, lft.w, acc.x);
            acc.y = fmaf(k0.y, mid.x, acc.y);
            acc.z = fmaf(k0.z, mid.y, acc.z);
            acc.w = fmaf(k0.w, mid.z, acc.w);
            // tap dx=1 (center column): dy==1 -> input0, else input
            acc.x = fmaf(k1.x, c.x, acc.x);
            acc.y = fmaf(k1.y, c.y, acc.y);
            acc.z = fmaf(k1.z, c.z, acc.z);
            acc.w = fmaf(k1.w, c.w, acc.w);
            // tap dx=2: cols x0+1..x0+4
            acc.x = fmaf(k2.x, mid.y, acc.x);
            acc.y = fmaf(k2.y, mid.z, acc.y);
            acc.z = fmaf(k2.z, mid.w, acc.z);
            acc.w = fmaf(k2.w, rgt.x, acc.w);
        }

        __stcs(&out4[pix_base], acc);
    }
}

extern "C" void kernel_launch(void* const* d_in, const int* in_sizes, int n_in,
                              void* d_out, int out_size)
{
    const float4* ker4   = (const float4*)d_in[0];
    const float4* inp4   = (const float4*)d_in[1];
    const float4* inp0_4 = (const float4*)d_in[2];
    float4*       out4   = (float4*)d_out;

    cspn_kernel<<<NBLK, THREADS>>>(ker4, inp4, inp0_4, out4);
}

// round 13
// speedup vs baseline: 1.0316x; 1.0051x over previous
#include <cuda_runtime.h>

// CSPN 3x3 propagation (BS=16, H=352, W=1216, f32) — FINAL, converged.
//
// out[b,y,x] = sum_{t!=4} kernel[b,t,y,x] * input_pad[b, y+t/3-1, x+t%3-1]
//            + kernel[b,4,y,x] * input0[b,y,x]
//
// Pure HBM streamer: 328.7 MB compulsory traffic (kernel tensor 246.5 MB,
// read once). Best repeatable 43.49 us = 7.56 TB/s = 94.5% of 8 TB/s spec;
// identical-code rerun spread ±0.7 us (NAT DVFS). Gap to the 41.1 us floor
// is DRAM R/W turnaround (10:1 mix) + refresh — not code-addressable.
//
// Verified design points (one bench round each):
//  - 1 float4/thread, 32 regs -> full 2048 threads/SM occupancy.
//    Wider threads (R3) and row-pairing (R6) both regressed via occupancy
//    loss: resident-warp count dominates per-thread MLP on this chip.
//  - __ldcs on the stream-once kernel tensor + __stcs stores keep L2 for
//    the 9x-reused input rows (R2: -5.9 us). __ldlu equivalent (R8).
//  - Persistent one-resident-wave grid removes the wave-tail (R5: -2.3 us).
//    592 blocks x 512 threads = 4 blocks/SM x 148 SMs.

#define BS 16
#define H  352
#define W  1216
#define W4 (W / 4)   // 304

#define NSM     148
#define THREADS 512
#define BLKSM   4
#define NBLK    (NSM * BLKSM)   // 592

__global__ __launch_bounds__(THREADS, BLKSM) void cspn_kernel(
    const float4* __restrict__ ker4,    // [BS, 9, H, W4]
    const float4* __restrict__ inp4,    // [BS, H, W4]
    const float4* __restrict__ inp0_4,  // [BS, H, W4]
    float4*       __restrict__ out4)    // [BS, H, W4]
{
    const unsigned total  = BS * H * W4;            // 1,712,128
    const unsigned stride = gridDim.x * blockDim.x; // 303,104

    const float4 z = make_float4(0.f, 0.f, 0.f, 0.f);
    const size_t ker_plane = (size_t)H * W4;

    for (unsigned tid = blockIdx.x * blockDim.x + threadIdx.x;
         tid < total; tid += stride)
    {
        unsigned x4 = tid % W4;
        unsigned y  = (tid / W4) % H;
        unsigned b  = tid / (W4 * H);

        const size_t ker_base = (size_t)b * 9 * ker_plane + (size_t)y * W4 + x4;
        const size_t pix_base = ((size_t)b * H + y) * W4 + x4;

        bool has_l = (x4 > 0);
        bool has_r = (x4 < W4 - 1);

        float4 acc = z;

#pragma unroll
        for (int dy = 0; dy < 3; dy++) {
            int yy = (int)y + dy - 1;
            bool vy = (yy >= 0) && (yy < H);
            const float4* rp = inp4 + ((size_t)b * H + (vy ? yy : 0)) * W4;

            float4 lft = (vy && has_l) ? __ldg(rp + x4 - 1) : z;
            float4 mid =  vy           ? __ldg(rp + x4)     : z;
            float4 rgt = (vy && has_r) ? __ldg(rp + x4 + 1) : z;

            // kernel tensor: read exactly once -> evict-first streaming
            float4 k0 = __ldcs(&ker4[ker_base + (size_t)(dy * 3 + 0) * ker_plane]);
            float4 k1 = __ldcs(&ker4[ker_base + (size_t)(dy * 3 + 1) * ker_plane]);
            float4 k2 = __ldcs(&ker4[ker_base + (size_t)(dy * 3 + 2) * ker_plane]);

            // center tap (t=4): kernel * input0 instead of kernel * input
            float4 c = (dy == 1) ? __ldg(&inp0_4[pix_base]) : mid;

            // tap dx=0: cols x0-1..x0+2
            acc.x = fmaf(k0.x, lft.w, acc.x);
            acc.y = fmaf(k0.y, mid.x, acc.y);
            acc.z = fmaf(k0.z, mid.y, acc.z);
            acc.w = fmaf(k0.w, mid.z, acc.w);
            // tap dx=1 (center column): dy==1 -> input0, else input
            acc.x = fmaf(k1.x, c.x, acc.x);
            acc.y = fmaf(k1.y, c.y, acc.y);
            acc.z = fmaf(k1.z, c.z, acc.z);
            acc.w = fmaf(k1.w, c.w, acc.w);
            // tap dx=2: cols x0+1..x0+4
            acc.x = fmaf(k2.x, mid.y, acc.x);
            acc.y = fmaf(k2.y, mid.z, acc.y);
            acc.z = fmaf(k2.z, mid.w, acc.z);
            acc.w = fmaf(k2.w, rgt.x, acc.w);
        }

        __stcs(&out4[pix_base], acc);
    }
}

extern "C" void kernel_launch(void* const* d_in, const int* in_sizes, int n_in,
                              void* d_out, int out_size)
{
    const float4* ker4   = (const float4*)d_in[0];
    const float4* inp4   = (const float4*)d_in[1];
    const float4* inp0_4 = (const float4*)d_in[2];
    float4*       out4   = (float4*)d_out;

    cspn_kernel<<<NBLK, THREADS>>>(ker4, inp4, inp0_4, out4);
}

// round 14
// speedup vs baseline: 1.0324x; 1.0007x over previous
#include <cuda_runtime.h>

// CSPN 3x3 propagation (BS=16, H=352, W=1216, f32) — FINAL, converged.
//
// out[b,y,x] = sum_{t!=4} kernel[b,t,y,x] * input_pad[b, y+t/3-1, x+t%3-1]
//            + kernel[b,4,y,x] * input0[b,y,x]
//
// Pure HBM streamer: 328.7 MB compulsory traffic (kernel tensor 246.5 MB,
// read once). Best repeatable 43.49 us = 7.56 TB/s = 94.5% of 8 TB/s spec;
// five identical-code reruns spread ±0.7 us (NAT DVFS). Gap to the 41.1 us
// floor is DRAM R/W turnaround (10:1 mix) + refresh — not code-addressable.
//
// Verified design points (one bench round each):
//  - 1 float4/thread, 32 regs -> full 2048 threads/SM occupancy.
//    Wider threads (R3) and row-pairing (R6) both regressed via occupancy
//    loss: resident-warp count dominates per-thread MLP on this chip.
//  - __ldcs on the stream-once kernel tensor + __stcs stores keep L2 for
//    the 9x-reused input rows (R2: -5.9 us). __ldlu equivalent (R8).
//  - Persistent one-resident-wave grid removes the wave-tail (R5: -2.3 us).
//    592 blocks x 512 threads = 4 blocks/SM x 148 SMs.

#define BS 16
#define H  352
#define W  1216
#define W4 (W / 4)   // 304

#define NSM     148
#define THREADS 512
#define BLKSM   4
#define NBLK    (NSM * BLKSM)   // 592

__global__ __launch_bounds__(THREADS, BLKSM) void cspn_kernel(
    const float4* __restrict__ ker4,    // [BS, 9, H, W4]
    const float4* __restrict__ inp4,    // [BS, H, W4]
    const float4* __restrict__ inp0_4,  // [BS, H, W4]
    float4*       __restrict__ out4)    // [BS, H, W4]
{
    const unsigned total  = BS * H * W4;            // 1,712,128
    const unsigned stride = gridDim.x * blockDim.x; // 303,104

    const float4 z = make_float4(0.f, 0.f, 0.f, 0.f);
    const size_t ker_plane = (size_t)H * W4;

    for (unsigned tid = blockIdx.x * blockDim.x + threadIdx.x;
         tid < total; tid += stride)
    {
        unsigned x4 = tid % W4;
        unsigned y  = (tid / W4) % H;
        unsigned b  = tid / (W4 * H);

        const size_t ker_base = (size_t)b * 9 * ker_plane + (size_t)y * W4 + x4;
        const size_t pix_base = ((size_t)b * H + y) * W4 + x4;

        bool has_l = (x4 > 0);
        bool has_r = (x4 < W4 - 1);

        float4 acc = z;

#pragma unroll
        for (int dy = 0; dy < 3; dy++) {
            int yy = (int)y + dy - 1;
            bool vy = (yy >= 0) && (yy < H);
            const float4* rp = inp4 + ((size_t)b * H + (vy ? yy : 0)) * W4;

            float4 lft = (vy && has_l) ? __ldg(rp + x4 - 1) : z;
            float4 mid =  vy           ? __ldg(rp + x4)     : z;
            float4 rgt = (vy && has_r) ? __ldg(rp + x4 + 1) : z;

            // kernel tensor: read exactly once -> evict-first streaming
            float4 k0 = __ldcs(&ker4[ker_base + (size_t)(dy * 3 + 0) * ker_plane]);
            float4 k1 = __ldcs(&ker4[ker_base + (size_t)(dy * 3 + 1) * ker_plane]);
            float4 k2 = __ldcs(&ker4[ker_base + (size_t)(dy * 3 + 2) * ker_plane]);

            // center tap (t=4): kernel * input0 instead of kernel * input
            float4 c = (dy == 1) ? __ldg(&inp0_4[pix_base]) : mid;

            // tap dx=0: cols x0-1..x0+2
            acc.x = fmaf(k0.x, lft.w, acc.x);
            acc.y = fmaf(k0.y, mid.x, acc.y);
            acc.z = fmaf(k0.z, mid.y, acc.z);
            acc.w = fmaf(k0.w, mid.z, acc.w);
            // tap dx=1 (center column): dy==1 -> input0, else input
            acc.x = fmaf(k1.x, c.x, acc.x);
            acc.y = fmaf(k1.y, c.y, acc.y);
            acc.z = fmaf(k1.z, c.z, acc.z);
            acc.w = fmaf(k1.w, c.w, acc.w);
            // tap dx=2: cols x0+1..x0+4
            acc.x = fmaf(k2.x, mid.y, acc.x);
            acc.y = fmaf(k2.y, mid.z, acc.y);
            acc.z = fmaf(k2.z, mid.w, acc.z);
            acc.w = fmaf(k2.w, rgt.x, acc.w);
        }

        __stcs(&out4[pix_base], acc);
    }
}

extern "C" void kernel_launch(void* const* d_in, const int* in_sizes, int n_in,
                              void* d_out, int out_size)
{
    const float4* ker4   = (const float4*)d_in[0];
    const float4* inp4   = (const float4*)d_in[1];
    const float4* inp0_4 = (const float4*)d_in[2];
    float4*       out4   = (float4*)d_out;

    cspn_kernel<<<NBLK, THREADS>>>(ker4, inp4, inp0_4, out4);
}